// round 7
// baseline (speedup 1.0000x reference)
#include <cuda_runtime.h>
#include <cuda_fp16.h>
#include <cuda_bf16.h>
#include <math.h>

// ---------------------------------------------------------------------------
// GraphSAGE (3x SAGEConv mean + ReLU, softmax) on GB300 — round 7.
//  * GEMMs: round-5 config (2 CTAs/SM overlap; split-fp16 mma.sync).
//  * Aggregation: uint4 (16B) gathers, 2-4 edges per load instruction,
//    shfl-combined partial sums. Grid sized to one resident wave.
//  * deg zeroed at END of frame (device arrays start zero) -> agg1 is the
//    5th kernel launch and lands in the ncu profile slot.
// ---------------------------------------------------------------------------

#define MAXN 100000
#define MAXE 1600000

__device__ int    g_deg[MAXN];          // zero-initialized; re-zeroed each frame
__device__ int    g_rowptr[MAXN + 1];
__device__ int    g_cursor[MAXN];
__device__ int    g_colidx[MAXE];
__device__ float  g_invdeg[MAXN];
__device__ float  g_S[(size_t)MAXN * 128];       // self-projection (+bias), fp32
__device__ __half g_P[(size_t)MAXN * 128];       // neighbor-projection, fp16
__device__ __half g_hsplit[(size_t)MAXN * 256];  // hidden, (hi|lo) split fp16

static __device__ __forceinline__ unsigned su32(const void* p) {
    return (unsigned)__cvta_generic_to_shared(p);
}

#define LDSM_X4(r, a)                                                          \
    asm volatile("ldmatrix.sync.aligned.m8n8.x4.shared.b16 {%0,%1,%2,%3}, [%4];" \
                 : "=r"((r)[0]), "=r"((r)[1]), "=r"((r)[2]), "=r"((r)[3]) : "r"(a))

#define LDSM_X4T(r, a)                                                         \
    asm volatile("ldmatrix.sync.aligned.m8n8.x4.trans.shared.b16 {%0,%1,%2,%3}, [%4];" \
                 : "=r"((r)[0]), "=r"((r)[1]), "=r"((r)[2]), "=r"((r)[3]) : "r"(a))

#define MMA16816(d, a, b0, b1)                                                 \
    asm volatile("mma.sync.aligned.m16n8k16.row.col.f32.f16.f16.f32 "          \
                 "{%0,%1,%2,%3}, {%4,%5,%6,%7}, {%8,%9}, {%0,%1,%2,%3};"       \
                 : "+f"((d)[0]), "+f"((d)[1]), "+f"((d)[2]), "+f"((d)[3])      \
                 : "r"((a)[0]), "r"((a)[1]), "r"((a)[2]), "r"((a)[3]),         \
                   "r"(b0), "r"(b1))

// ---------------------------- CSR construction ----------------------------

__global__ void zero_int_kernel(int* p, int n) {
    int i = blockIdx.x * blockDim.x + threadIdx.x;
    if (i < n) p[i] = 0;
}

__global__ void count_deg_kernel(const int* __restrict__ dst, int* __restrict__ deg, int E) {
    int e = blockIdx.x * blockDim.x + threadIdx.x;
    if (e < E) atomicAdd(&deg[__ldg(&dst[e])], 1);
}

__global__ void scan_deg_kernel(const int* __restrict__ deg, int* __restrict__ rowptr,
                                int* __restrict__ cursor, float* __restrict__ invdeg, int n) {
    __shared__ int ssum[1024];
    int tid = threadIdx.x;
    int chunk = (n + 1023) / 1024;
    int lo = tid * chunk;
    int hi = lo + chunk; if (hi > n) hi = n;
    if (lo > n) lo = n;

    int sum = 0;
    for (int i = lo; i < hi; ++i) sum += deg[i];
    ssum[tid] = sum;
    __syncthreads();
    for (int off = 1; off < 1024; off <<= 1) {
        int v = (tid >= off) ? ssum[tid - off] : 0;
        __syncthreads();
        ssum[tid] += v;
        __syncthreads();
    }
    int run = ssum[tid] - sum;  // exclusive prefix
    for (int i = lo; i < hi; ++i) {
        rowptr[i] = run;
        cursor[i] = run;
        float d = (float)deg[i];
        invdeg[i] = 1.0f / fmaxf(d, 1.0f);
        run += deg[i];
    }
    if (tid == 1023) rowptr[n] = ssum[1023];
}

__global__ void fill_csr_kernel(const int* __restrict__ src, const int* __restrict__ dst,
                                int* __restrict__ cursor, int* __restrict__ colidx, int E) {
    int e = blockIdx.x * blockDim.x + threadIdx.x;
    if (e < E) {
        int d = __ldg(&dst[e]);
        int p = atomicAdd(&cursor[d], 1);
        colidx[p] = __ldg(&src[e]);
    }
}

// ------------------- aggregation (mean) with fused epilogue ----------------
// warp per node, uint4 (16B) gathers. t = S[i] + mean_j P[j].
// D=128: 16 lanes per row -> 2 edges/instruction; combine via shfl_xor(16).
// D=64:   8 lanes per row -> 4 edges/instruction; combine via shfl 8,16.
// ACT 0: relu(t) stored (hi|lo) split fp16.  ACT 1: softmax(t) fp32 (D=64).

static __device__ __forceinline__ void acc8(float* a, uint4 u) {
    float2 f;
    f = __half22float2(*(const __half2*)&u.x); a[0] += f.x; a[1] += f.y;
    f = __half22float2(*(const __half2*)&u.y); a[2] += f.x; a[3] += f.y;
    f = __half22float2(*(const __half2*)&u.z); a[4] += f.x; a[5] += f.y;
    f = __half22float2(*(const __half2*)&u.w); a[6] += f.x; a[7] += f.y;
}

template <int D, int ACT>
__global__ void aggregate_ep(const __half* __restrict__ P, const float* __restrict__ S,
                             const int* __restrict__ rowptr, const int* __restrict__ colidx,
                             const float* __restrict__ invdeg, void* __restrict__ Yv, int n) {
    int warp = (blockIdx.x * blockDim.x + threadIdx.x) >> 5;
    int lane = threadIdx.x & 31;
    int nwarps = (gridDim.x * blockDim.x) >> 5;

    for (int i = warp; i < n; i += nwarps) {
        int jb = __ldg(&rowptr[i]);
        int e  = __ldg(&rowptr[i + 1]);
        float inv = __ldg(&invdeg[i]);
        float acc[8];
#pragma unroll
        for (int k = 0; k < 8; ++k) acc[k] = 0.f;

        if (D == 128) {
            int h = lane >> 4;        // edge slot within pair
            int s = lane & 15;        // 16B chunk within row
            int j = jb;
            for (; j + 7 < e; j += 8) {
                int c0 = __ldg(&colidx[j + h]);
                int c1 = __ldg(&colidx[j + 2 + h]);
                int c2 = __ldg(&colidx[j + 4 + h]);
                int c3 = __ldg(&colidx[j + 6 + h]);
                uint4 u0 = __ldg((const uint4*)(P + (size_t)c0 * 128) + s);
                uint4 u1 = __ldg((const uint4*)(P + (size_t)c1 * 128) + s);
                uint4 u2 = __ldg((const uint4*)(P + (size_t)c2 * 128) + s);
                uint4 u3 = __ldg((const uint4*)(P + (size_t)c3 * 128) + s);
                acc8(acc, u0); acc8(acc, u1); acc8(acc, u2); acc8(acc, u3);
            }
            for (; j + 1 < e; j += 2) {
                int c = __ldg(&colidx[j + h]);
                uint4 u = __ldg((const uint4*)(P + (size_t)c * 128) + s);
                acc8(acc, u);
            }
            if (j < e) {
                int c = __ldg(&colidx[j]);
                uint4 u = __ldg((const uint4*)(P + (size_t)c * 128) + s);
                if (h == 0) acc8(acc, u);
            }
#pragma unroll
            for (int k = 0; k < 8; ++k) acc[k] += __shfl_xor_sync(0xffffffffu, acc[k], 16);

            const float* Srow = S + (size_t)i * 128 + s * 8;
            float4 sv0 = __ldg((const float4*)Srow);
            float4 sv1 = __ldg((const float4*)Srow + 1);
            float t[8];
            t[0] = fmaxf(fmaf(acc[0], inv, sv0.x), 0.f);
            t[1] = fmaxf(fmaf(acc[1], inv, sv0.y), 0.f);
            t[2] = fmaxf(fmaf(acc[2], inv, sv0.z), 0.f);
            t[3] = fmaxf(fmaf(acc[3], inv, sv0.w), 0.f);
            t[4] = fmaxf(fmaf(acc[4], inv, sv1.x), 0.f);
            t[5] = fmaxf(fmaf(acc[5], inv, sv1.y), 0.f);
            t[6] = fmaxf(fmaf(acc[6], inv, sv1.z), 0.f);
            t[7] = fmaxf(fmaf(acc[7], inv, sv1.w), 0.f);
            __half* Y = (__half*)Yv + (size_t)i * 256;
            if (h == 0) {
                __half2 p0 = __floats2half2_rn(t[0], t[1]);
                __half2 p1 = __floats2half2_rn(t[2], t[3]);
                __half2 p2 = __floats2half2_rn(t[4], t[5]);
                __half2 p3 = __floats2half2_rn(t[6], t[7]);
                *(uint4*)(Y + s * 8) = make_uint4(*(unsigned*)&p0, *(unsigned*)&p1,
                                                  *(unsigned*)&p2, *(unsigned*)&p3);
            } else {
                __half2 q0, q1, q2, q3;
                {
                    __half a0 = __float2half_rn(t[0]), a1 = __float2half_rn(t[1]);
                    __half a2 = __float2half_rn(t[2]), a3 = __float2half_rn(t[3]);
                    __half a4 = __float2half_rn(t[4]), a5 = __float2half_rn(t[5]);
                    __half a6 = __float2half_rn(t[6]), a7 = __float2half_rn(t[7]);
                    q0 = __halves2half2(__float2half_rn(t[0] - __half2float(a0)),
                                        __float2half_rn(t[1] - __half2float(a1)));
                    q1 = __halves2half2(__float2half_rn(t[2] - __half2float(a2)),
                                        __float2half_rn(t[3] - __half2float(a3)));
                    q2 = __halves2half2(__float2half_rn(t[4] - __half2float(a4)),
                                        __float2half_rn(t[5] - __half2float(a5)));
                    q3 = __halves2half2(__float2half_rn(t[6] - __half2float(a6)),
                                        __float2half_rn(t[7] - __half2float(a7)));
                }
                *(uint4*)(Y + 128 + s * 8) = make_uint4(*(unsigned*)&q0, *(unsigned*)&q1,
                                                        *(unsigned*)&q2, *(unsigned*)&q3);
            }
        } else {  // D == 64
            int q = lane >> 3;        // edge slot within quad
            int s = lane & 7;         // 16B chunk within row
            int j = jb;
            for (; j + 15 < e; j += 16) {
                int c0 = __ldg(&colidx[j + q]);
                int c1 = __ldg(&colidx[j + 4 + q]);
                int c2 = __ldg(&colidx[j + 8 + q]);
                int c3 = __ldg(&colidx[j + 12 + q]);
                uint4 u0 = __ldg((const uint4*)(P + (size_t)c0 * 64) + s);
                uint4 u1 = __ldg((const uint4*)(P + (size_t)c1 * 64) + s);
                uint4 u2 = __ldg((const uint4*)(P + (size_t)c2 * 64) + s);
                uint4 u3 = __ldg((const uint4*)(P + (size_t)c3 * 64) + s);
                acc8(acc, u0); acc8(acc, u1); acc8(acc, u2); acc8(acc, u3);
            }
            for (; j + 3 < e; j += 4) {
                int c = __ldg(&colidx[j + q]);
                uint4 u = __ldg((const uint4*)(P + (size_t)c * 64) + s);
                acc8(acc, u);
            }
            if (j < e) {
                int rem = e - j;      // 1..3
                int c = __ldg(&colidx[j + (q < rem ? q : 0)]);
                uint4 u = __ldg((const uint4*)(P + (size_t)c * 64) + s);
                if (q < rem) acc8(acc, u);
            }
#pragma unroll
            for (int k = 0; k < 8; ++k) {
                acc[k] += __shfl_xor_sync(0xffffffffu, acc[k], 8);
                acc[k] += __shfl_xor_sync(0xffffffffu, acc[k], 16);
            }

            const float* Srow = S + (size_t)i * 64 + s * 8;
            float4 sv0 = __ldg((const float4*)Srow);
            float4 sv1 = __ldg((const float4*)Srow + 1);
            float t[8];
            t[0] = fmaf(acc[0], inv, sv0.x);
            t[1] = fmaf(acc[1], inv, sv0.y);
            t[2] = fmaf(acc[2], inv, sv0.z);
            t[3] = fmaf(acc[3], inv, sv0.w);
            t[4] = fmaf(acc[4], inv, sv1.x);
            t[5] = fmaf(acc[5], inv, sv1.y);
            t[6] = fmaf(acc[6], inv, sv1.z);
            t[7] = fmaf(acc[7], inv, sv1.w);
            if (ACT == 0) {
#pragma unroll
                for (int k = 0; k < 8; ++k) t[k] = fmaxf(t[k], 0.f);
                __half* Y = (__half*)Yv + (size_t)i * 128;
                if (q == 0) {
                    __half2 p0 = __floats2half2_rn(t[0], t[1]);
                    __half2 p1 = __floats2half2_rn(t[2], t[3]);
                    __half2 p2 = __floats2half2_rn(t[4], t[5]);
                    __half2 p3 = __floats2half2_rn(t[6], t[7]);
                    *(uint4*)(Y + s * 8) = make_uint4(*(unsigned*)&p0, *(unsigned*)&p1,
                                                      *(unsigned*)&p2, *(unsigned*)&p3);
                } else if (q == 1) {
                    __half a[8];
#pragma unroll
                    for (int k = 0; k < 8; ++k) a[k] = __float2half_rn(t[k]);
                    __half2 q0 = __halves2half2(__float2half_rn(t[0] - __half2float(a[0])),
                                                __float2half_rn(t[1] - __half2float(a[1])));
                    __half2 q1 = __halves2half2(__float2half_rn(t[2] - __half2float(a[2])),
                                                __float2half_rn(t[3] - __half2float(a[3])));
                    __half2 q2 = __halves2half2(__float2half_rn(t[4] - __half2float(a[4])),
                                                __float2half_rn(t[5] - __half2float(a[5])));
                    __half2 q3 = __halves2half2(__float2half_rn(t[6] - __half2float(a[6])),
                                                __float2half_rn(t[7] - __half2float(a[7])));
                    *(uint4*)(Y + 64 + s * 8) = make_uint4(*(unsigned*)&q0, *(unsigned*)&q1,
                                                           *(unsigned*)&q2, *(unsigned*)&q3);
                }
            } else {
                // softmax over 64 cols: reduce across the 8 s-lanes
                float m = t[0];
#pragma unroll
                for (int k = 1; k < 8; ++k) m = fmaxf(m, t[k]);
#pragma unroll
                for (int off = 1; off < 8; off <<= 1)
                    m = fmaxf(m, __shfl_xor_sync(0xffffffffu, m, off));
                float ex[8];
                float sm = 0.f;
#pragma unroll
                for (int k = 0; k < 8; ++k) { ex[k] = __expf(t[k] - m); sm += ex[k]; }
#pragma unroll
                for (int off = 1; off < 8; off <<= 1)
                    sm += __shfl_xor_sync(0xffffffffu, sm, off);
                float rinv = 1.0f / sm;
                if (q == 0) {
                    float* O = (float*)Yv + (size_t)i * 64 + s * 8;
                    *(float4*)O       = make_float4(ex[0] * rinv, ex[1] * rinv, ex[2] * rinv, ex[3] * rinv);
                    *((float4*)O + 1) = make_float4(ex[4] * rinv, ex[5] * rinv, ex[6] * rinv, ex[7] * rinv);
                }
            }
        }
    }
}

// ----------------------- tensor-core projection GEMM -----------------------
// Round-5 config: no cp.async; 2 CTAs/SM provide the load/MMA overlap.
// PRESPLIT: A fp16 (hi|lo) width 2K (raw copy). Else fp32, split in-kernel.

template <int K, bool PRESPLIT>
__global__ __launch_bounds__(256, 2) void gemm_mma(
    const void* __restrict__ Av, const float* __restrict__ Ws,
    const float* __restrict__ Wn, const float* __restrict__ bias,
    float* __restrict__ S, __half* __restrict__ P,
    int n, int HF, int nh) {
    constexpr int LDA = 2 * K + 8;
    constexpr int LDB = 136;
    extern __shared__ __half smh[];
    __half* sA = smh;                 // [64][LDA]
    __half* sB = smh + 64 * LDA;      // [2K][LDB]

    int tid = threadIdx.x;
    int h = blockIdx.x % nh;
    int colbase = h * 128;
    int t0 = blockIdx.x / nh;
    int tstep = gridDim.x / nh;

    for (int idx = tid; idx < K * 128; idx += 256) {
        int k = idx >> 7, c = idx & 127;
        int gc = colbase + c;
        float w = (gc < HF) ? __ldg(&Ws[k * HF + gc]) : __ldg(&Wn[k * HF + gc - HF]);
        __half wh = __float2half_rn(w);
        __half wl = __float2half_rn(w - __half2float(wh));
        sB[k * LDB + c] = wh;
        sB[(K + k) * LDB + c] = wl;
    }

    int lane = tid & 31;
    int warp = tid >> 5;
    int wm = warp & 3;
    int wnh = warp >> 2;

    int arow = wm * 16 + (lane & 15);
    int acolsel = (lane >> 4) * 8;
    int brow = lane & 15;
    int bcol = wnh * 64 + (lane >> 4) * 8;

    float2 binit[8];
#pragma unroll
    for (int nt = 0; nt < 8; ++nt) {
        int gc = colbase + wnh * 64 + nt * 8 + (lane & 3) * 2;
        float b0 = 0.f, b1 = 0.f;
        if (gc < HF) { b0 = __ldg(&bias[gc]); b1 = __ldg(&bias[gc + 1]); }
        binit[nt] = make_float2(b0, b1);
    }

    int ntiles = (n + 63) >> 6;
    for (int t = t0; t < ntiles; t += tstep) {
        int row0g = t * 64;
        __syncthreads();

        if (PRESPLIT) {
            constexpr int CPR = 2 * K / 8;
            const __half* A = (const __half*)Av;
            for (int idx = tid; idx < 64 * CPR; idx += 256) {
                int r = idx / CPR, c = idx % CPR;
                int gr = row0g + r;
                uint4 v = make_uint4(0u, 0u, 0u, 0u);
                if (gr < n) v = __ldg((const uint4*)(A + (size_t)gr * 2 * K) + c);
                *(uint4*)&sA[r * LDA + c * 8] = v;
            }
        } else {
            const float* A = (const float*)Av;
            for (int idx = tid; idx < 64 * (K / 4); idx += 256) {
                int r  = idx / (K / 4);
                int k4 = idx % (K / 4);
                int gr = row0g + r;
                float4 v = make_float4(0.f, 0.f, 0.f, 0.f);
                if (gr < n) v = __ldg((const float4*)(A + (size_t)gr * K) + k4);
                __half h0 = __float2half_rn(v.x);
                __half h1 = __float2half_rn(v.y);
                __half h2 = __float2half_rn(v.z);
                __half h3 = __float2half_rn(v.w);
                __half l0 = __float2half_rn(v.x - __half2float(h0));
                __half l1 = __float2half_rn(v.y - __half2float(h1));
                __half l2 = __float2half_rn(v.z - __half2float(h2));
                __half l3 = __float2half_rn(v.w - __half2float(h3));
                __half2* ph = (__half2*)&sA[r * LDA + k4 * 4];
                ph[0] = __halves2half2(h0, h1);
                ph[1] = __halves2half2(h2, h3);
                __half2* pl = (__half2*)&sA[r * LDA + K + k4 * 4];
                pl[0] = __halves2half2(l0, l1);
                pl[1] = __halves2half2(l2, l3);
            }
        }
        __syncthreads();

        float acc[8][4];
#pragma unroll
        for (int nt = 0; nt < 8; ++nt) {
            acc[nt][0] = binit[nt].x; acc[nt][1] = binit[nt].y;
            acc[nt][2] = binit[nt].x; acc[nt][3] = binit[nt].y;
        }

#pragma unroll
        for (int k16 = 0; k16 < K; k16 += 16) {
            unsigned ah[4], al[4];
            LDSM_X4(ah, su32(&sA[arow * LDA + k16 + acolsel]));
            LDSM_X4(al, su32(&sA[arow * LDA + K + k16 + acolsel]));
#pragma unroll
            for (int tt = 0; tt < 4; ++tt) {
                unsigned bh[4], bl[4];
                LDSM_X4T(bh, su32(&sB[(k16 + brow) * LDB + bcol + tt * 16]));
                MMA16816(acc[tt * 2],     ah, bh[0], bh[1]);
                MMA16816(acc[tt * 2 + 1], ah, bh[2], bh[3]);
                MMA16816(acc[tt * 2],     al, bh[0], bh[1]);
                MMA16816(acc[tt * 2 + 1], al, bh[2], bh[3]);
                LDSM_X4T(bl, su32(&sB[(K + k16 + brow) * LDB + bcol + tt * 16]));
                MMA16816(acc[tt * 2],     ah, bl[0], bl[1]);
                MMA16816(acc[tt * 2 + 1], ah, bl[2], bl[3]);
            }
        }

        int r0 = row0g + wm * 16 + (lane >> 2);
#pragma unroll
        for (int nt = 0; nt < 8; ++nt) {
            int gc = colbase + wnh * 64 + nt * 8 + (lane & 3) * 2;
            if (gc < HF) {
                if (r0 < n)
                    *(float2*)(S + (size_t)r0 * HF + gc) = make_float2(acc[nt][0], acc[nt][1]);
                if (r0 + 8 < n)
                    *(float2*)(S + (size_t)(r0 + 8) * HF + gc) = make_float2(acc[nt][2], acc[nt][3]);
            } else {
                int pc = gc - HF;
                if (r0 < n)
                    *(__half2*)(P + (size_t)r0 * HF + pc) = __floats2half2_rn(acc[nt][0], acc[nt][1]);
                if (r0 + 8 < n)
                    *(__half2*)(P + (size_t)(r0 + 8) * HF + pc) = __floats2half2_rn(acc[nt][2], acc[nt][3]);
            }
        }
    }
}

// ---------------------------------------------------------------------------

extern "C" void kernel_launch(void* const* d_in, const int* in_sizes, int n_in,
                              void* d_out, int out_size) {
    const float* x   = (const float*)d_in[0];
    const int*   src = (const int*)d_in[1];
    const int*   dst = (const int*)d_in[2];
    const float* ws1 = (const float*)d_in[3];
    const float* wn1 = (const float*)d_in[4];
    const float* b1  = (const float*)d_in[5];
    const float* ws2 = (const float*)d_in[6];
    const float* wn2 = (const float*)d_in[7];
    const float* b2  = (const float*)d_in[8];
    const float* ws3 = (const float*)d_in[9];
    const float* wn3 = (const float*)d_in[10];
    const float* b3  = (const float*)d_in[11];
    float* out = (float*)d_out;

    int N = in_sizes[0] / 128;
    int E = in_sizes[1];

    int *deg, *rowptr, *cursor, *colidx;
    float *invdeg, *Sb;
    __half *Pb, *hs;
    cudaGetSymbolAddress((void**)&deg,    g_deg);
    cudaGetSymbolAddress((void**)&rowptr, g_rowptr);
    cudaGetSymbolAddress((void**)&cursor, g_cursor);
    cudaGetSymbolAddress((void**)&colidx, g_colidx);
    cudaGetSymbolAddress((void**)&invdeg, g_invdeg);
    cudaGetSymbolAddress((void**)&Sb,     g_S);
    cudaGetSymbolAddress((void**)&Pb,     g_P);
    cudaGetSymbolAddress((void**)&hs,     g_hsplit);

    const int SMEM_K128 = (64 * (2 * 128 + 8) + 2 * 128 * 136) * 2;  // 103424
    const int SMEM_K64  = (64 * (2 * 64 + 8) + 2 * 64 * 136) * 2;    //  52224
    cudaFuncSetAttribute((const void*)gemm_mma<128, false>,
                         cudaFuncAttributeMaxDynamicSharedMemorySize, SMEM_K128);
    cudaFuncSetAttribute((const void*)gemm_mma<128, true>,
                         cudaFuncAttributeMaxDynamicSharedMemorySize, SMEM_K128);
    cudaFuncSetAttribute((const void*)gemm_mma<64, true>,
                         cudaFuncAttributeMaxDynamicSharedMemorySize, SMEM_K64);

    static cudaStream_t s_csr = 0;
    static cudaEvent_t e_fork = 0, e_join = 0, e_zero = 0;
    if (!s_csr) {
        cudaStreamCreateWithFlags(&s_csr, cudaStreamNonBlocking);
        cudaEventCreateWithFlags(&e_fork, cudaEventDisableTiming);
        cudaEventCreateWithFlags(&e_join, cudaEventDisableTiming);
        cudaEventCreateWithFlags(&e_zero, cudaEventDisableTiming);
    }

    // ---- fork: CSR build on side stream (deg is zero at entry: static init
    //      on the first call, end-of-frame zeroing on every call) ----
    cudaEventRecord(e_fork, 0);
    cudaStreamWaitEvent(s_csr, e_fork, 0);
    count_deg_kernel<<<(E + 255) / 256, 256, 0, s_csr>>>(dst, deg, E);   // launch 1
    scan_deg_kernel<<<1, 1024, 0, s_csr>>>(deg, rowptr, cursor, invdeg, N); // 2
    fill_csr_kernel<<<(E + 255) / 256, 256, 0, s_csr>>>(src, dst, cursor, colidx, E); // 3
    cudaEventRecord(e_join, s_csr);

    // ---- main: layer-1 GEMM (fp32 X, in-kernel split) ----
    gemm_mma<128, false><<<296, 256, SMEM_K128>>>(x, ws1, wn1, b1, Sb, Pb, N, 128, 2); // 4
    cudaStreamWaitEvent(0, e_join, 0);

    const int AGG_BLOCKS = 1184;   // one resident wave (148 SMs x 8 blocks)

    // ---- layer 1 (launch 5 -> ncu profile slot) ----
    aggregate_ep<128, 0><<<AGG_BLOCKS, 256>>>(Pb, Sb, rowptr, colidx, invdeg, hs, N); // 5

    // re-zero deg for the next frame (after scan_deg is done with it)
    zero_int_kernel<<<(N + 255) / 256, 256, 0, s_csr>>>(deg, N);          // 6
    cudaEventRecord(e_zero, s_csr);

    // ---- layer 2 ----
    gemm_mma<128, true><<<296, 256, SMEM_K128>>>(hs, ws2, wn2, b2, Sb, Pb, N, 64, 1); // 7
    aggregate_ep<64, 0><<<AGG_BLOCKS, 256>>>(Pb, Sb, rowptr, colidx, invdeg, hs, N);  // 8
    // ---- layer 3 ----
    gemm_mma<64, true><<<296, 256, SMEM_K64>>>(hs, ws3, wn3, b3, Sb, Pb, N, 64, 1);   // 9
    aggregate_ep<64, 1><<<AGG_BLOCKS, 256>>>(Pb, Sb, rowptr, colidx, invdeg, out, N); // 10

    cudaStreamWaitEvent(0, e_zero, 0);  // rejoin side stream before capture ends
}

// round 8
// speedup vs baseline: 1.0402x; 1.0402x over previous
#include <cuda_runtime.h>
#include <cuda_fp16.h>
#include <cuda_bf16.h>
#include <math.h>

// ---------------------------------------------------------------------------
// GraphSAGE (3x SAGEConv mean + ReLU, softmax) on GB300 — round 8.
//  * Round-5 GEMM/scheduling (best so far, 442.3us) + deeper aggregation
//    unroll (16 edges in flight per warp) to fix the latency-bound gather.
// ---------------------------------------------------------------------------

#define MAXN 100000
#define MAXE 1600000

__device__ int    g_deg[MAXN];
__device__ int    g_rowptr[MAXN + 1];
__device__ int    g_cursor[MAXN];
__device__ int    g_colidx[MAXE];
__device__ float  g_invdeg[MAXN];
__device__ float  g_S[(size_t)MAXN * 128];       // self-projection (+bias), fp32
__device__ __half g_P[(size_t)MAXN * 128];       // neighbor-projection, fp16
__device__ __half g_hsplit[(size_t)MAXN * 256];  // hidden, (hi|lo) split fp16

static __device__ __forceinline__ unsigned su32(const void* p) {
    return (unsigned)__cvta_generic_to_shared(p);
}

#define LDSM_X4(r, a)                                                          \
    asm volatile("ldmatrix.sync.aligned.m8n8.x4.shared.b16 {%0,%1,%2,%3}, [%4];" \
                 : "=r"((r)[0]), "=r"((r)[1]), "=r"((r)[2]), "=r"((r)[3]) : "r"(a))

#define LDSM_X4T(r, a)                                                         \
    asm volatile("ldmatrix.sync.aligned.m8n8.x4.trans.shared.b16 {%0,%1,%2,%3}, [%4];" \
                 : "=r"((r)[0]), "=r"((r)[1]), "=r"((r)[2]), "=r"((r)[3]) : "r"(a))

#define MMA16816(d, a, b0, b1)                                                 \
    asm volatile("mma.sync.aligned.m16n8k16.row.col.f32.f16.f16.f32 "          \
                 "{%0,%1,%2,%3}, {%4,%5,%6,%7}, {%8,%9}, {%0,%1,%2,%3};"       \
                 : "+f"((d)[0]), "+f"((d)[1]), "+f"((d)[2]), "+f"((d)[3])      \
                 : "r"((a)[0]), "r"((a)[1]), "r"((a)[2]), "r"((a)[3]),         \
                   "r"(b0), "r"(b1))

// ---------------------------- CSR construction ----------------------------

__global__ void count_deg_kernel(const int* __restrict__ dst, int* __restrict__ deg, int E) {
    int e = blockIdx.x * blockDim.x + threadIdx.x;
    if (e < E) atomicAdd(&deg[__ldg(&dst[e])], 1);
}

__global__ void scan_deg_kernel(const int* __restrict__ deg, int* __restrict__ rowptr,
                                int* __restrict__ cursor, float* __restrict__ invdeg, int n) {
    __shared__ int ssum[1024];
    int tid = threadIdx.x;
    int chunk = (n + 1023) / 1024;
    int lo = tid * chunk;
    int hi = lo + chunk; if (hi > n) hi = n;
    if (lo > n) lo = n;

    int sum = 0;
    for (int i = lo; i < hi; ++i) sum += deg[i];
    ssum[tid] = sum;
    __syncthreads();
    for (int off = 1; off < 1024; off <<= 1) {
        int v = (tid >= off) ? ssum[tid - off] : 0;
        __syncthreads();
        ssum[tid] += v;
        __syncthreads();
    }
    int run = ssum[tid] - sum;  // exclusive prefix
    for (int i = lo; i < hi; ++i) {
        rowptr[i] = run;
        cursor[i] = run;
        float d = (float)deg[i];
        invdeg[i] = 1.0f / fmaxf(d, 1.0f);
        run += deg[i];
    }
    if (tid == 1023) rowptr[n] = ssum[1023];
}

__global__ void fill_csr_kernel(const int* __restrict__ src, const int* __restrict__ dst,
                                int* __restrict__ cursor, int* __restrict__ colidx, int E) {
    int e = blockIdx.x * blockDim.x + threadIdx.x;
    if (e < E) {
        int d = __ldg(&dst[e]);
        int p = atomicAdd(&cursor[d], 1);
        colidx[p] = __ldg(&src[e]);
    }
}

// ------------------- aggregation (mean) with fused epilogue ----------------
// warp per node; 16-deep edge unroll for MLP. t = S[i] + mean_j P[j].
// ACT 0: relu(t) stored (hi|lo) split fp16.  ACT 1: softmax(t) fp32 (D=64).

template <int D, int ACT>
__global__ void aggregate_ep(const __half* __restrict__ P, const float* __restrict__ S,
                             const int* __restrict__ rowptr, const int* __restrict__ colidx,
                             const float* __restrict__ invdeg, void* __restrict__ Yv, int n) {
    int warp = (blockIdx.x * blockDim.x + threadIdx.x) >> 5;
    int lane = threadIdx.x & 31;
    int nwarps = (gridDim.x * blockDim.x) >> 5;

    for (int i = warp; i < n; i += nwarps) {
        int s = __ldg(&rowptr[i]);
        int e = __ldg(&rowptr[i + 1]);
        float inv = __ldg(&invdeg[i]);

        if (D == 128) {
            float4 acc = make_float4(0.f, 0.f, 0.f, 0.f);
            int j = s;
            for (; j + 15 < e; j += 16) {
                int c[16];
#pragma unroll
                for (int q = 0; q < 16; ++q) c[q] = __ldg(&colidx[j + q]);
#pragma unroll
                for (int q = 0; q < 16; ++q) {
                    uint2 u = __ldg((const uint2*)(P + (size_t)c[q] * 128) + lane);
                    float2 a = __half22float2(*(const __half2*)&u.x);
                    float2 b = __half22float2(*(const __half2*)&u.y);
                    acc.x += a.x; acc.y += a.y; acc.z += b.x; acc.w += b.y;
                }
            }
            for (; j + 3 < e; j += 4) {
                int c[4];
#pragma unroll
                for (int q = 0; q < 4; ++q) c[q] = __ldg(&colidx[j + q]);
#pragma unroll
                for (int q = 0; q < 4; ++q) {
                    uint2 u = __ldg((const uint2*)(P + (size_t)c[q] * 128) + lane);
                    float2 a = __half22float2(*(const __half2*)&u.x);
                    float2 b = __half22float2(*(const __half2*)&u.y);
                    acc.x += a.x; acc.y += a.y; acc.z += b.x; acc.w += b.y;
                }
            }
            for (; j < e; ++j) {
                int c0 = __ldg(&colidx[j]);
                uint2 u = __ldg((const uint2*)(P + (size_t)c0 * 128) + lane);
                float2 a = __half22float2(*(const __half2*)&u.x);
                float2 b = __half22float2(*(const __half2*)&u.y);
                acc.x += a.x; acc.y += a.y; acc.z += b.x; acc.w += b.y;
            }
            float4 sv = __ldg((const float4*)(S + (size_t)i * 128) + lane);
            float ox = fmaxf(fmaf(acc.x, inv, sv.x), 0.f);
            float oy = fmaxf(fmaf(acc.y, inv, sv.y), 0.f);
            float oz = fmaxf(fmaf(acc.z, inv, sv.z), 0.f);
            float ow = fmaxf(fmaf(acc.w, inv, sv.w), 0.f);
            __half hx = __float2half_rn(ox), hy = __float2half_rn(oy);
            __half hz = __float2half_rn(oz), hw = __float2half_rn(ow);
            __half lx = __float2half_rn(ox - __half2float(hx));
            __half ly = __float2half_rn(oy - __half2float(hy));
            __half lz = __float2half_rn(oz - __half2float(hz));
            __half lw = __float2half_rn(ow - __half2float(hw));
            __half* Y = (__half*)Yv + (size_t)i * 256;
            __half2 hi01 = __halves2half2(hx, hy), hi23 = __halves2half2(hz, hw);
            __half2 lo01 = __halves2half2(lx, ly), lo23 = __halves2half2(lz, lw);
            *(uint2*)(Y + 4 * lane)       = make_uint2(*(unsigned*)&hi01, *(unsigned*)&hi23);
            *(uint2*)(Y + 128 + 4 * lane) = make_uint2(*(unsigned*)&lo01, *(unsigned*)&lo23);
        } else {  // D == 64
            float2 acc = make_float2(0.f, 0.f);
            int j = s;
            for (; j + 15 < e; j += 16) {
                int c[16];
#pragma unroll
                for (int q = 0; q < 16; ++q) c[q] = __ldg(&colidx[j + q]);
#pragma unroll
                for (int q = 0; q < 16; ++q) {
                    unsigned u = __ldg((const unsigned*)(P + (size_t)c[q] * 64) + lane);
                    float2 f = __half22float2(*(const __half2*)&u);
                    acc.x += f.x; acc.y += f.y;
                }
            }
            for (; j + 3 < e; j += 4) {
                int c[4];
#pragma unroll
                for (int q = 0; q < 4; ++q) c[q] = __ldg(&colidx[j + q]);
#pragma unroll
                for (int q = 0; q < 4; ++q) {
                    unsigned u = __ldg((const unsigned*)(P + (size_t)c[q] * 64) + lane);
                    float2 f = __half22float2(*(const __half2*)&u);
                    acc.x += f.x; acc.y += f.y;
                }
            }
            for (; j < e; ++j) {
                int c0 = __ldg(&colidx[j]);
                unsigned u = __ldg((const unsigned*)(P + (size_t)c0 * 64) + lane);
                float2 f = __half22float2(*(const __half2*)&u);
                acc.x += f.x; acc.y += f.y;
            }
            float2 sv = __ldg((const float2*)(S + (size_t)i * 64) + lane);
            float tx = fmaf(acc.x, inv, sv.x);
            float ty = fmaf(acc.y, inv, sv.y);
            if (ACT == 0) {
                float ox = fmaxf(tx, 0.f), oy = fmaxf(ty, 0.f);
                __half hx = __float2half_rn(ox), hy = __float2half_rn(oy);
                __half lx = __float2half_rn(ox - __half2float(hx));
                __half ly = __float2half_rn(oy - __half2float(hy));
                __half* Y = (__half*)Yv + (size_t)i * 128;
                __half2 hp = __halves2half2(hx, hy);
                __half2 lp = __halves2half2(lx, ly);
                *(unsigned*)(Y + 2 * lane)      = *(unsigned*)&hp;
                *(unsigned*)(Y + 64 + 2 * lane) = *(unsigned*)&lp;
            } else {
                float m = fmaxf(tx, ty);
#pragma unroll
                for (int o = 16; o; o >>= 1) m = fmaxf(m, __shfl_xor_sync(0xffffffffu, m, o));
                float ex = __expf(tx - m);
                float ey = __expf(ty - m);
                float sm = ex + ey;
#pragma unroll
                for (int o = 16; o; o >>= 1) sm += __shfl_xor_sync(0xffffffffu, sm, o);
                float rinv = 1.0f / sm;
                ((float2*)((float*)Yv + (size_t)i * 64))[lane] = make_float2(ex * rinv, ey * rinv);
            }
        }
    }
}

// ----------------------- tensor-core projection GEMM -----------------------
// Round-5 config: 2 CTAs/SM provide load/MMA overlap.
// PRESPLIT: A fp16 (hi|lo) width 2K (raw copy). Else fp32, split in-kernel.

template <int K, bool PRESPLIT>
__global__ __launch_bounds__(256, 2) void gemm_mma(
    const void* __restrict__ Av, const float* __restrict__ Ws,
    const float* __restrict__ Wn, const float* __restrict__ bias,
    float* __restrict__ S, __half* __restrict__ P,
    int n, int HF, int nh) {
    constexpr int LDA = 2 * K + 8;
    constexpr int LDB = 136;
    extern __shared__ __half smh[];
    __half* sA = smh;                 // [64][LDA]
    __half* sB = smh + 64 * LDA;      // [2K][LDB]

    int tid = threadIdx.x;
    int h = blockIdx.x % nh;
    int colbase = h * 128;
    int t0 = blockIdx.x / nh;
    int tstep = gridDim.x / nh;

    for (int idx = tid; idx < K * 128; idx += 256) {
        int k = idx >> 7, c = idx & 127;
        int gc = colbase + c;
        float w = (gc < HF) ? __ldg(&Ws[k * HF + gc]) : __ldg(&Wn[k * HF + gc - HF]);
        __half wh = __float2half_rn(w);
        __half wl = __float2half_rn(w - __half2float(wh));
        sB[k * LDB + c] = wh;
        sB[(K + k) * LDB + c] = wl;
    }

    int lane = tid & 31;
    int warp = tid >> 5;
    int wm = warp & 3;
    int wnh = warp >> 2;

    int arow = wm * 16 + (lane & 15);
    int acolsel = (lane >> 4) * 8;
    int brow = lane & 15;
    int bcol = wnh * 64 + (lane >> 4) * 8;

    float2 binit[8];
#pragma unroll
    for (int nt = 0; nt < 8; ++nt) {
        int gc = colbase + wnh * 64 + nt * 8 + (lane & 3) * 2;
        float b0 = 0.f, b1 = 0.f;
        if (gc < HF) { b0 = __ldg(&bias[gc]); b1 = __ldg(&bias[gc + 1]); }
        binit[nt] = make_float2(b0, b1);
    }

    int ntiles = (n + 63) >> 6;
    for (int t = t0; t < ntiles; t += tstep) {
        int row0g = t * 64;
        __syncthreads();

        if (PRESPLIT) {
            constexpr int CPR = 2 * K / 8;
            const __half* A = (const __half*)Av;
            for (int idx = tid; idx < 64 * CPR; idx += 256) {
                int r = idx / CPR, c = idx % CPR;
                int gr = row0g + r;
                uint4 v = make_uint4(0u, 0u, 0u, 0u);
                if (gr < n) v = __ldg((const uint4*)(A + (size_t)gr * 2 * K) + c);
                *(uint4*)&sA[r * LDA + c * 8] = v;
            }
        } else {
            const float* A = (const float*)Av;
            for (int idx = tid; idx < 64 * (K / 4); idx += 256) {
                int r  = idx / (K / 4);
                int k4 = idx % (K / 4);
                int gr = row0g + r;
                float4 v = make_float4(0.f, 0.f, 0.f, 0.f);
                if (gr < n) v = __ldg((const float4*)(A + (size_t)gr * K) + k4);
                __half h0 = __float2half_rn(v.x);
                __half h1 = __float2half_rn(v.y);
                __half h2 = __float2half_rn(v.z);
                __half h3 = __float2half_rn(v.w);
                __half l0 = __float2half_rn(v.x - __half2float(h0));
                __half l1 = __float2half_rn(v.y - __half2float(h1));
                __half l2 = __float2half_rn(v.z - __half2float(h2));
                __half l3 = __float2half_rn(v.w - __half2float(h3));
                __half2* ph = (__half2*)&sA[r * LDA + k4 * 4];
                ph[0] = __halves2half2(h0, h1);
                ph[1] = __halves2half2(h2, h3);
                __half2* pl = (__half2*)&sA[r * LDA + K + k4 * 4];
                pl[0] = __halves2half2(l0, l1);
                pl[1] = __halves2half2(l2, l3);
            }
        }
        __syncthreads();

        float acc[8][4];
#pragma unroll
        for (int nt = 0; nt < 8; ++nt) {
            acc[nt][0] = binit[nt].x; acc[nt][1] = binit[nt].y;
            acc[nt][2] = binit[nt].x; acc[nt][3] = binit[nt].y;
        }

#pragma unroll
        for (int k16 = 0; k16 < K; k16 += 16) {
            unsigned ah[4], al[4];
            LDSM_X4(ah, su32(&sA[arow * LDA + k16 + acolsel]));
            LDSM_X4(al, su32(&sA[arow * LDA + K + k16 + acolsel]));
#pragma unroll
            for (int tt = 0; tt < 4; ++tt) {
                unsigned bh[4], bl[4];
                LDSM_X4T(bh, su32(&sB[(k16 + brow) * LDB + bcol + tt * 16]));
                MMA16816(acc[tt * 2],     ah, bh[0], bh[1]);
                MMA16816(acc[tt * 2 + 1], ah, bh[2], bh[3]);
                MMA16816(acc[tt * 2],     al, bh[0], bh[1]);
                MMA16816(acc[tt * 2 + 1], al, bh[2], bh[3]);
                LDSM_X4T(bl, su32(&sB[(K + k16 + brow) * LDB + bcol + tt * 16]));
                MMA16816(acc[tt * 2],     ah, bl[0], bl[1]);
                MMA16816(acc[tt * 2 + 1], ah, bl[2], bl[3]);
            }
        }

        int r0 = row0g + wm * 16 + (lane >> 2);
#pragma unroll
        for (int nt = 0; nt < 8; ++nt) {
            int gc = colbase + wnh * 64 + nt * 8 + (lane & 3) * 2;
            if (gc < HF) {
                if (r0 < n)
                    *(float2*)(S + (size_t)r0 * HF + gc) = make_float2(acc[nt][0], acc[nt][1]);
                if (r0 + 8 < n)
                    *(float2*)(S + (size_t)(r0 + 8) * HF + gc) = make_float2(acc[nt][2], acc[nt][3]);
            } else {
                int pc = gc - HF;
                if (r0 < n)
                    *(__half2*)(P + (size_t)r0 * HF + pc) = __floats2half2_rn(acc[nt][0], acc[nt][1]);
                if (r0 + 8 < n)
                    *(__half2*)(P + (size_t)(r0 + 8) * HF + pc) = __floats2half2_rn(acc[nt][2], acc[nt][3]);
            }
        }
    }
}

// ---------------------------------------------------------------------------

extern "C" void kernel_launch(void* const* d_in, const int* in_sizes, int n_in,
                              void* d_out, int out_size) {
    const float* x   = (const float*)d_in[0];
    const int*   src = (const int*)d_in[1];
    const int*   dst = (const int*)d_in[2];
    const float* ws1 = (const float*)d_in[3];
    const float* wn1 = (const float*)d_in[4];
    const float* b1  = (const float*)d_in[5];
    const float* ws2 = (const float*)d_in[6];
    const float* wn2 = (const float*)d_in[7];
    const float* b2  = (const float*)d_in[8];
    const float* ws3 = (const float*)d_in[9];
    const float* wn3 = (const float*)d_in[10];
    const float* b3  = (const float*)d_in[11];
    float* out = (float*)d_out;

    int N = in_sizes[0] / 128;
    int E = in_sizes[1];

    int *deg, *rowptr, *cursor, *colidx;
    float *invdeg, *Sb;
    __half *Pb, *hs;
    cudaGetSymbolAddress((void**)&deg,    g_deg);
    cudaGetSymbolAddress((void**)&rowptr, g_rowptr);
    cudaGetSymbolAddress((void**)&cursor, g_cursor);
    cudaGetSymbolAddress((void**)&colidx, g_colidx);
    cudaGetSymbolAddress((void**)&invdeg, g_invdeg);
    cudaGetSymbolAddress((void**)&Sb,     g_S);
    cudaGetSymbolAddress((void**)&Pb,     g_P);
    cudaGetSymbolAddress((void**)&hs,     g_hsplit);

    const int SMEM_K128 = (64 * (2 * 128 + 8) + 2 * 128 * 136) * 2;  // 103424
    const int SMEM_K64  = (64 * (2 * 64 + 8) + 2 * 64 * 136) * 2;    //  52224
    cudaFuncSetAttribute((const void*)gemm_mma<128, false>,
                         cudaFuncAttributeMaxDynamicSharedMemorySize, SMEM_K128);
    cudaFuncSetAttribute((const void*)gemm_mma<128, true>,
                         cudaFuncAttributeMaxDynamicSharedMemorySize, SMEM_K128);
    cudaFuncSetAttribute((const void*)gemm_mma<64, true>,
                         cudaFuncAttributeMaxDynamicSharedMemorySize, SMEM_K64);

    static cudaStream_t s_csr = 0;
    static cudaEvent_t e_fork = 0, e_join = 0;
    if (!s_csr) {
        cudaStreamCreateWithFlags(&s_csr, cudaStreamNonBlocking);
        cudaEventCreateWithFlags(&e_fork, cudaEventDisableTiming);
        cudaEventCreateWithFlags(&e_join, cudaEventDisableTiming);
    }

    // ---- fork: CSR build on side stream ----
    cudaEventRecord(e_fork, 0);
    cudaStreamWaitEvent(s_csr, e_fork, 0);
    cudaMemsetAsync(deg, 0, N * sizeof(int), s_csr);
    count_deg_kernel<<<(E + 255) / 256, 256, 0, s_csr>>>(dst, deg, E);
    scan_deg_kernel<<<1, 1024, 0, s_csr>>>(deg, rowptr, cursor, invdeg, N);
    fill_csr_kernel<<<(E + 255) / 256, 256, 0, s_csr>>>(src, dst, cursor, colidx, E);
    cudaEventRecord(e_join, s_csr);

    // ---- main: layer-1 GEMM (fp32 X, in-kernel split) ----
    gemm_mma<128, false><<<296, 256, SMEM_K128>>>(x, ws1, wn1, b1, Sb, Pb, N, 128, 2);
    cudaStreamWaitEvent(0, e_join, 0);

    const int AGG_BLOCKS = 2048;

    // ---- layer 1 ----
    aggregate_ep<128, 0><<<AGG_BLOCKS, 256>>>(Pb, Sb, rowptr, colidx, invdeg, hs, N);
    // ---- layer 2 ----
    gemm_mma<128, true><<<296, 256, SMEM_K128>>>(hs, ws2, wn2, b2, Sb, Pb, N, 64, 1);
    aggregate_ep<64, 0><<<AGG_BLOCKS, 256>>>(Pb, Sb, rowptr, colidx, invdeg, hs, N);
    // ---- layer 3 ----
    gemm_mma<64, true><<<296, 256, SMEM_K64>>>(hs, ws3, wn3, b3, Sb, Pb, N, 64, 1);
    aggregate_ep<64, 1><<<AGG_BLOCKS, 256>>>(Pb, Sb, rowptr, colidx, invdeg, out, N);
}